// round 4
// baseline (speedup 1.0000x reference)
#include <cuda_runtime.h>

// Two-stage deterministic reduction for 0.5 * sum((d1-d2)^2), with PDL overlap.
// Stage 1: 1184 blocks (one full wave: 148 SMs x 8 x 256 thr), streaming float4
//          loads, one partial per block; each block triggers programmatic launch
//          completion after its fenced partial store.
// Stage 2: launched with ProgrammaticStreamSerialization -> its launch latency
//          overlaps stage 1. It grid-dependency-syncs, then sums the 1184
//          partials in fixed order (bitwise deterministic) and writes out[0].

#define GRID_BLOCKS 1184          // multiple of 4 -> partials readable as float4
#define BLOCK_THREADS 256
#define FIN_THREADS 128

__device__ float g_partials[GRID_BLOCKS];

__global__ void __launch_bounds__(BLOCK_THREADS)
mse_partial_kernel(const float4* __restrict__ a,
                   const float4* __restrict__ b,
                   int n4)
{
    float acc = 0.0f;
    const int stride = gridDim.x * blockDim.x;
    int i = blockIdx.x * blockDim.x + threadIdx.x;

    #pragma unroll 4
    for (; i < n4; i += stride) {
        float4 x = __ldcs(a + i);   // streaming: read-once data
        float4 y = __ldcs(b + i);
        float d0 = x.x - y.x;
        float d1 = x.y - y.y;
        float d2 = x.z - y.z;
        float d3 = x.w - y.w;
        acc = fmaf(d0, d0, acc);
        acc = fmaf(d1, d1, acc);
        acc = fmaf(d2, d2, acc);
        acc = fmaf(d3, d3, acc);
    }

    // Warp reduce
    #pragma unroll
    for (int o = 16; o > 0; o >>= 1)
        acc += __shfl_down_sync(0xffffffffu, acc, o);

    __shared__ float smem[BLOCK_THREADS / 32];
    const int lane = threadIdx.x & 31;
    const int wid  = threadIdx.x >> 5;
    if (lane == 0) smem[wid] = acc;
    __syncthreads();

    if (wid == 0) {
        acc = (lane < BLOCK_THREADS / 32) ? smem[lane] : 0.0f;
        #pragma unroll
        for (int o = 16; o > 0; o >>= 1)
            acc += __shfl_down_sync(0xffffffffu, acc, o);
        if (lane == 0) {
            g_partials[blockIdx.x] = acc;
            __threadfence();
        }
    }
    // Signal the dependent (finisher) kernel that this block's partial is
    // published. Finisher may start once every block has triggered/exited.
    cudaTriggerProgrammaticLaunchCompletion();
}

__global__ void __launch_bounds__(FIN_THREADS)
mse_final_kernel(float* __restrict__ out, int n4_times4, int n,
                 const float* __restrict__ a_s, const float* __restrict__ b_s)
{
    // Wait for all stage-1 blocks' fenced partial stores to be visible.
    cudaGridDependencySynchronize();

    const float4* p4 = (const float4*)g_partials;
    const int NV = GRID_BLOCKS / 4;   // 296

    float acc = 0.0f;
    #pragma unroll
    for (int j = threadIdx.x; j < NV; j += FIN_THREADS) {
        float4 v = p4[j];
        acc += (v.x + v.y) + (v.z + v.w);
    }

    // Scalar tail of the input (n not multiple of 4) — thread 0 only.
    if (threadIdx.x == 0) {
        for (int t = n4_times4; t < n; ++t) {
            float d = a_s[t] - b_s[t];
            acc = fmaf(d, d, acc);
        }
    }

    #pragma unroll
    for (int o = 16; o > 0; o >>= 1)
        acc += __shfl_down_sync(0xffffffffu, acc, o);

    __shared__ float smem[FIN_THREADS / 32];
    const int lane = threadIdx.x & 31;
    const int wid  = threadIdx.x >> 5;
    if (lane == 0) smem[wid] = acc;
    __syncthreads();

    if (threadIdx.x == 0) {
        float fin = (smem[0] + smem[1]) + (smem[2] + smem[3]);
        out[0] = 0.5f * fin;
    }
}

extern "C" void kernel_launch(void* const* d_in, const int* in_sizes, int n_in,
                              void* d_out, int out_size)
{
    const float* d1 = (const float*)d_in[0];
    const float* d2 = (const float*)d_in[1];
    float* out = (float*)d_out;

    const int n  = in_sizes[0];   // 40,000,000
    const int n4 = n >> 2;

    mse_partial_kernel<<<GRID_BLOCKS, BLOCK_THREADS>>>(
        (const float4*)d1, (const float4*)d2, n4);

    // Finisher with programmatic dependent launch: launch overlaps stage 1.
    cudaLaunchConfig_t cfg = {};
    cfg.gridDim  = dim3(1, 1, 1);
    cfg.blockDim = dim3(FIN_THREADS, 1, 1);
    cfg.dynamicSmemBytes = 0;
    cfg.stream = (cudaStream_t)0;   // legacy default stream (captured by harness)

    cudaLaunchAttribute attr[1];
    attr[0].id = cudaLaunchAttributeProgrammaticStreamSerialization;
    attr[0].val.programmaticStreamSerializationAllowed = 1;
    cfg.attrs = attr;
    cfg.numAttrs = 1;

    int n4t4 = n4 << 2;
    cudaLaunchKernelEx(&cfg, mse_final_kernel, out, n4t4, n, d1, d2);
}

// round 5
// speedup vs baseline: 1.0050x; 1.0050x over previous
#include <cuda_runtime.h>

// Two-stage deterministic reduction for 0.5 * sum((d1-d2)^2).
// Stage 1: 1184 blocks (full wave: 148 SMs x 8 x 256 thr), streaming float4
//          loads; triggers programmatic launch completion AT KERNEL START so
//          the finisher becomes resident early. Each block publishes its
//          partial with a release (fence + atomic counter increment).
// Stage 2: PDL-launched 1-warp finisher that SPINS on the counter (fine-
//          grained: unblocks when the last partial lands, not at grid
//          teardown), sums partials in fixed order (bitwise deterministic),
//          writes out[0], resets the counter for the next graph replay.

#define GRID_BLOCKS 1184          // multiple of 4 -> partials readable as float4
#define BLOCK_THREADS 256

__device__ float g_partials[GRID_BLOCKS];
__device__ unsigned int g_counter = 0;

__global__ void __launch_bounds__(BLOCK_THREADS)
mse_partial_kernel(const float4* __restrict__ a,
                   const float4* __restrict__ b,
                   int n4)
{
    // Let the dependent finisher launch ASAP; it self-synchronizes via
    // g_counter, so early launch is safe.
    cudaTriggerProgrammaticLaunchCompletion();

    float acc = 0.0f;
    const int stride = gridDim.x * blockDim.x;
    int i = blockIdx.x * blockDim.x + threadIdx.x;

    #pragma unroll 4
    for (; i < n4; i += stride) {
        float4 x = __ldcs(a + i);   // streaming: read-once data
        float4 y = __ldcs(b + i);
        float d0 = x.x - y.x;
        float d1 = x.y - y.y;
        float d2 = x.z - y.z;
        float d3 = x.w - y.w;
        acc = fmaf(d0, d0, acc);
        acc = fmaf(d1, d1, acc);
        acc = fmaf(d2, d2, acc);
        acc = fmaf(d3, d3, acc);
    }

    // Warp reduce
    #pragma unroll
    for (int o = 16; o > 0; o >>= 1)
        acc += __shfl_down_sync(0xffffffffu, acc, o);

    __shared__ float smem[BLOCK_THREADS / 32];
    const int lane = threadIdx.x & 31;
    const int wid  = threadIdx.x >> 5;
    if (lane == 0) smem[wid] = acc;
    __syncthreads();

    if (wid == 0) {
        acc = (lane < BLOCK_THREADS / 32) ? smem[lane] : 0.0f;
        #pragma unroll
        for (int o = 16; o > 0; o >>= 1)
            acc += __shfl_down_sync(0xffffffffu, acc, o);
        if (lane == 0) {
            g_partials[blockIdx.x] = acc;         // publish partial
            __threadfence();                      // order store before counter
            atomicAdd(&g_counter, 1u);            // release signal
        }
    }
}

__global__ void __launch_bounds__(32)
mse_final_kernel(float* __restrict__ out, int n4_times4, int n,
                 const float* __restrict__ a_s, const float* __restrict__ b_s)
{
    // Fine-grained wait: proceed the moment the 1184th partial is published.
    if (threadIdx.x == 0) {
        volatile unsigned int* ctr = &g_counter;
        while (*ctr != GRID_BLOCKS) { }
    }
    __syncwarp();
    __threadfence();   // acquire: make partial stores visible

    const float4* p4 = (const float4*)g_partials;
    const int NV = GRID_BLOCKS / 4;   // 296 -> 9-10 independent loads/lane

    float acc = 0.0f;
    #pragma unroll
    for (int j = threadIdx.x; j < NV; j += 32) {
        float4 v = p4[j];
        acc += (v.x + v.y) + (v.z + v.w);
    }

    // Scalar tail of the input (n not multiple of 4) — lane 0 only.
    if (threadIdx.x == 0) {
        for (int t = n4_times4; t < n; ++t) {
            float d = a_s[t] - b_s[t];
            acc = fmaf(d, d, acc);
        }
    }

    #pragma unroll
    for (int o = 16; o > 0; o >>= 1)
        acc += __shfl_down_sync(0xffffffffu, acc, o);

    if (threadIdx.x == 0) {
        out[0] = 0.5f * acc;
        __threadfence();
        g_counter = 0;   // reset for next graph replay (stream-ordered)
    }
}

extern "C" void kernel_launch(void* const* d_in, const int* in_sizes, int n_in,
                              void* d_out, int out_size)
{
    const float* d1 = (const float*)d_in[0];
    const float* d2 = (const float*)d_in[1];
    float* out = (float*)d_out;

    const int n  = in_sizes[0];   // 40,000,000
    const int n4 = n >> 2;

    mse_partial_kernel<<<GRID_BLOCKS, BLOCK_THREADS>>>(
        (const float4*)d1, (const float4*)d2, n4);

    // Finisher with programmatic dependent launch; it self-syncs on g_counter.
    cudaLaunchConfig_t cfg = {};
    cfg.gridDim  = dim3(1, 1, 1);
    cfg.blockDim = dim3(32, 1, 1);
    cfg.dynamicSmemBytes = 0;
    cfg.stream = (cudaStream_t)0;

    cudaLaunchAttribute attr[1];
    attr[0].id = cudaLaunchAttributeProgrammaticStreamSerialization;
    attr[0].val.programmaticStreamSerializationAllowed = 1;
    cfg.attrs = attr;
    cfg.numAttrs = 1;

    int n4t4 = n4 << 2;
    cudaLaunchKernelEx(&cfg, mse_final_kernel, out, n4t4, n, d1, d2);
}

// round 6
// speedup vs baseline: 1.0068x; 1.0019x over previous
#include <cuda_runtime.h>

// Two-stage deterministic reduction for 0.5 * sum((d1-d2)^2).
// Stage 1: 4736 blocks (4x oversubscription: 148 SMs x 8 resident x 4 waves,
//          continuously backfilled) -> tail-balances the ~10% between-SM L2-die
//          spread that a single-wave launch fully exposes. Fixed blockIdx->data
//          mapping + fixed summation order -> bitwise deterministic.
// Stage 2: 256-thread finisher, float4 loads of the 4736 partials, fixed order.

#define GRID_BLOCKS 4736          // multiple of 4 -> partials readable as float4
#define BLOCK_THREADS 256
#define FIN_THREADS 256

__device__ float g_partials[GRID_BLOCKS];

__global__ void __launch_bounds__(BLOCK_THREADS)
mse_partial_kernel(const float4* __restrict__ a,
                   const float4* __restrict__ b,
                   int n4)
{
    float acc = 0.0f;
    const int stride = gridDim.x * blockDim.x;
    int i = blockIdx.x * blockDim.x + threadIdx.x;

    #pragma unroll 4
    for (; i < n4; i += stride) {
        float4 x = __ldcs(a + i);   // streaming: read-once data
        float4 y = __ldcs(b + i);
        float d0 = x.x - y.x;
        float d1 = x.y - y.y;
        float d2 = x.z - y.z;
        float d3 = x.w - y.w;
        acc = fmaf(d0, d0, acc);
        acc = fmaf(d1, d1, acc);
        acc = fmaf(d2, d2, acc);
        acc = fmaf(d3, d3, acc);
    }

    // Warp reduce
    #pragma unroll
    for (int o = 16; o > 0; o >>= 1)
        acc += __shfl_down_sync(0xffffffffu, acc, o);

    __shared__ float smem[BLOCK_THREADS / 32];
    const int lane = threadIdx.x & 31;
    const int wid  = threadIdx.x >> 5;
    if (lane == 0) smem[wid] = acc;
    __syncthreads();

    if (wid == 0) {
        acc = (lane < BLOCK_THREADS / 32) ? smem[lane] : 0.0f;
        #pragma unroll
        for (int o = 16; o > 0; o >>= 1)
            acc += __shfl_down_sync(0xffffffffu, acc, o);
        if (lane == 0) g_partials[blockIdx.x] = acc;
    }
}

__global__ void __launch_bounds__(FIN_THREADS)
mse_final_kernel(float* __restrict__ out, int n4_times4, int n,
                 const float* __restrict__ a_s, const float* __restrict__ b_s)
{
    // 4736 partials = 1184 float4; 256 threads -> ~5 independent loads each.
    const float4* p4 = (const float4*)g_partials;
    const int NV = GRID_BLOCKS / 4;   // 1184

    float acc = 0.0f;
    #pragma unroll
    for (int j = threadIdx.x; j < NV; j += FIN_THREADS) {
        float4 v = p4[j];
        acc += (v.x + v.y) + (v.z + v.w);
    }

    // Scalar tail of the input (n not multiple of 4) — thread 0 only.
    if (threadIdx.x == 0) {
        for (int t = n4_times4; t < n; ++t) {
            float d = a_s[t] - b_s[t];
            acc = fmaf(d, d, acc);
        }
    }

    #pragma unroll
    for (int o = 16; o > 0; o >>= 1)
        acc += __shfl_down_sync(0xffffffffu, acc, o);

    __shared__ float smem[FIN_THREADS / 32];
    const int lane = threadIdx.x & 31;
    const int wid  = threadIdx.x >> 5;
    if (lane == 0) smem[wid] = acc;
    __syncthreads();

    if (threadIdx.x == 0) {
        float fin = 0.0f;
        #pragma unroll
        for (int w = 0; w < FIN_THREADS / 32; ++w)
            fin += smem[w];
        out[0] = 0.5f * fin;
    }
}

extern "C" void kernel_launch(void* const* d_in, const int* in_sizes, int n_in,
                              void* d_out, int out_size)
{
    const float* d1 = (const float*)d_in[0];
    const float* d2 = (const float*)d_in[1];
    float* out = (float*)d_out;

    const int n  = in_sizes[0];   // 40,000,000
    const int n4 = n >> 2;

    mse_partial_kernel<<<GRID_BLOCKS, BLOCK_THREADS>>>(
        (const float4*)d1, (const float4*)d2, n4);
    mse_final_kernel<<<1, FIN_THREADS>>>(out, n4 << 2, n, d1, d2);
}